// round 1
// baseline (speedup 1.0000x reference)
#include <cuda_runtime.h>

#define HID 128
#define NN 100000
#define EE 600000

// ---------------- scratch (static device globals; no allocs) ----------------
__device__ float g_h   [(size_t)NN * HID];   // layer-0 input features
__device__ float g_h1  [(size_t)NN * HID];   // layer-1 output
__device__ float g_mean[(size_t)NN * HID];   // mean-aggregated features
__device__ float g_Bt  [4][HID * HID];       // WlT1, WrT1, WlT2, WrT2 (transposed)
__device__ int   g_cnt [NN];                 // in-degree
__device__ int   g_rowstart[NN];             // CSR row starts
__device__ int   g_cursor  [NN];             // fill cursors
__device__ int   g_csr [EE];                 // CSR: src per (dst-sorted) edge
__device__ int   g_bsum[256];                // scan block sums

// ---------------- CSR build ----------------
__global__ void k_zero_cnt(int n) {
    int i = blockIdx.x * blockDim.x + threadIdx.x;
    if (i < n) g_cnt[i] = 0;
}

__global__ void k_hist(const int* __restrict__ dst, int e) {
    int i = blockIdx.x * blockDim.x + threadIdx.x;
    if (i < e) atomicAdd(&g_cnt[dst[i]], 1);
}

__global__ void k_scanA(int n) {
    __shared__ int s[1024];
    int i = blockIdx.x * 1024 + threadIdx.x;
    int v = (i < n) ? g_cnt[i] : 0;
    s[threadIdx.x] = v;
    __syncthreads();
    #pragma unroll
    for (int off = 1; off < 1024; off <<= 1) {
        int t = (threadIdx.x >= off) ? s[threadIdx.x - off] : 0;
        __syncthreads();
        s[threadIdx.x] += t;
        __syncthreads();
    }
    if (i < n) g_rowstart[i] = s[threadIdx.x] - v;   // exclusive scan within block
    if (threadIdx.x == 1023) g_bsum[blockIdx.x] = s[1023];
}

__global__ void k_scanB(int nb) {
    int acc = 0;
    for (int b = 0; b < nb; b++) { int v = g_bsum[b]; g_bsum[b] = acc; acc += v; }
}

__global__ void k_scanC(int n) {
    int i = blockIdx.x * 1024 + threadIdx.x;
    if (i < n) {
        int rs = g_rowstart[i] + g_bsum[blockIdx.x];
        g_rowstart[i] = rs;
        g_cursor[i]   = rs;
    }
}

__global__ void k_fill(const int* __restrict__ src, const int* __restrict__ dst, int e) {
    int i = blockIdx.x * blockDim.x + threadIdx.x;
    if (i < e) {
        int p = atomicAdd(&g_cursor[dst[i]], 1);
        g_csr[p] = src[i];
    }
}

// ---------------- feature gather: h = emb[x] ----------------
__global__ void k_gather(const int* __restrict__ x, const float4* __restrict__ emb, int n) {
    int i = blockIdx.x * blockDim.x + threadIdx.x;
    int total = n * (HID / 4);
    if (i < total) {
        int node = i >> 5;
        int c    = i & 31;
        ((float4*)g_h)[i] = emb[(size_t)x[node] * 32 + c];
    }
}

// ---------------- weight transpose: Bt[k][j] = W[j][k] ----------------
__global__ void k_transpose(const float* __restrict__ W, int which) {
    int j = blockIdx.x;
    int k = threadIdx.x;
    g_Bt[which][k * HID + j] = W[j * HID + k];
}

// ---------------- mean aggregation (one warp per node) ----------------
__global__ void k_agg(int layer, int n) {
    int gw   = (blockIdx.x * blockDim.x + threadIdx.x) >> 5;
    int lane = threadIdx.x & 31;
    if (gw >= n) return;
    const float4* h4 = (const float4*)(layer ? g_h1 : g_h);
    int deg = g_cnt[gw];
    int st  = g_rowstart[gw];
    float4 acc = make_float4(0.f, 0.f, 0.f, 0.f);
    for (int e = 0; e < deg; e++) {
        int s = g_csr[st + e];
        float4 v = h4[(size_t)s * 32 + lane];
        acc.x += v.x; acc.y += v.y; acc.z += v.z; acc.w += v.w;
    }
    float sc = 1.0f / (float)max(deg, 1);
    acc.x *= sc; acc.y *= sc; acc.z *= sc; acc.w *= sc;
    ((float4*)g_mean)[(size_t)gw * 32 + lane] = acc;
}

// ---------------- fused dual GEMM + bias + relu ----------------
// out[r][j] = relu( sum_k mean[r][k]*Wl[j][k] + sum_k h[r][k]*Wr[j][k] + b[j] )
// Block: 256 threads = 8 warps, 64 rows x 128 cols per block.
// Warp w -> rows r0..r0+7, lane -> cols lane*4..lane*4+3.
__global__ __launch_bounds__(256) void k_gemm(int layer, const float* __restrict__ bias,
                                              float* __restrict__ outparam, int n) {
    const float* Am  = g_mean;
    const float* Ah  = layer ? g_h1 : g_h;
    const float* Btl = g_Bt[2 * layer];
    const float* Btr = g_Bt[2 * layer + 1];
    float* out = layer ? outparam : g_h1;

    int w    = threadIdx.x >> 5;
    int lane = threadIdx.x & 31;
    int r0   = blockIdx.x * 64 + w * 8;

    // clamped row offsets (tail block reads row n-1, stores are guarded)
    int off[8];
    #pragma unroll
    for (int i = 0; i < 8; i++) {
        int r = r0 + i; if (r > n - 1) r = n - 1;
        off[i] = r * HID;
    }

    float acc[8][4];
    float4 bv = __ldg((const float4*)bias + lane);
    #pragma unroll
    for (int i = 0; i < 8; i++) {
        acc[i][0] = bv.x; acc[i][1] = bv.y; acc[i][2] = bv.z; acc[i][3] = bv.w;
    }

    const float4* Bl4 = (const float4*)Btl;
    #pragma unroll 2
    for (int k = 0; k < HID; k++) {
        float4 b = __ldg(Bl4 + k * 32 + lane);
        #pragma unroll
        for (int i = 0; i < 8; i++) {
            float a = __ldg(Am + off[i] + k);   // warp-broadcast load
            acc[i][0] = fmaf(a, b.x, acc[i][0]);
            acc[i][1] = fmaf(a, b.y, acc[i][1]);
            acc[i][2] = fmaf(a, b.z, acc[i][2]);
            acc[i][3] = fmaf(a, b.w, acc[i][3]);
        }
    }

    const float4* Br4 = (const float4*)Btr;
    #pragma unroll 2
    for (int k = 0; k < HID; k++) {
        float4 b = __ldg(Br4 + k * 32 + lane);
        #pragma unroll
        for (int i = 0; i < 8; i++) {
            float a = __ldg(Ah + off[i] + k);
            acc[i][0] = fmaf(a, b.x, acc[i][0]);
            acc[i][1] = fmaf(a, b.y, acc[i][1]);
            acc[i][2] = fmaf(a, b.z, acc[i][2]);
            acc[i][3] = fmaf(a, b.w, acc[i][3]);
        }
    }

    #pragma unroll
    for (int i = 0; i < 8; i++) {
        int r = r0 + i;
        if (r < n) {
            float4 o;
            o.x = fmaxf(acc[i][0], 0.f);
            o.y = fmaxf(acc[i][1], 0.f);
            o.z = fmaxf(acc[i][2], 0.f);
            o.w = fmaxf(acc[i][3], 0.f);
            ((float4*)out)[(size_t)r * 32 + lane] = o;
        }
    }
}

// ---------------- launch ----------------
extern "C" void kernel_launch(void* const* d_in, const int* in_sizes, int n_in,
                              void* d_out, int out_size) {
    const int*   x    = (const int*)  d_in[0];
    const int*   ei   = (const int*)  d_in[1];
    const float* emb  = (const float*)d_in[2];
    const float* Wl1  = (const float*)d_in[3];
    const float* bl1  = (const float*)d_in[4];
    const float* Wr1  = (const float*)d_in[5];
    const float* Wl2  = (const float*)d_in[6];
    const float* bl2  = (const float*)d_in[7];
    const float* Wr2  = (const float*)d_in[8];

    int n = in_sizes[0];
    int e = in_sizes[1] / 2;
    const int* src = ei;
    const int* dst = ei + e;

    int nb = (n + 1023) / 1024;

    // CSR build (graph identical for both layers)
    k_zero_cnt<<<(n + 255) / 256, 256>>>(n);
    k_hist    <<<(e + 255) / 256, 256>>>(dst, e);
    k_scanA   <<<nb, 1024>>>(n);
    k_scanB   <<<1, 1>>>(nb);
    k_scanC   <<<nb, 1024>>>(n);
    k_fill    <<<(e + 255) / 256, 256>>>(src, dst, e);

    // h0 = emb[x], weight transposes
    k_gather<<<(n * 32 + 255) / 256, 256>>>(x, (const float4*)emb, n);
    k_transpose<<<128, 128>>>(Wl1, 0);
    k_transpose<<<128, 128>>>(Wr1, 1);
    k_transpose<<<128, 128>>>(Wl2, 2);
    k_transpose<<<128, 128>>>(Wr2, 3);

    // layer 1
    k_agg <<<(n + 7) / 8,   256>>>(0, n);
    k_gemm<<<(n + 63) / 64, 256>>>(0, bl1, (float*)d_out, n);  // writes g_h1

    // layer 2
    k_agg <<<(n + 7) / 8,   256>>>(1, n);
    k_gemm<<<(n + 63) / 64, 256>>>(1, bl2, (float*)d_out, n);  // writes d_out
}

// round 2
// speedup vs baseline: 2.1877x; 2.1877x over previous
#include <cuda_runtime.h>
#include <cuda_bf16.h>
#include <stdint.h>

#define HID 128
#define NN 100000
#define EE 600000

// ---------------- scratch (static device globals; no allocs) ----------------
__device__ float g_h   [(size_t)NN * HID];   // layer-0 input features
__device__ float g_h1  [(size_t)NN * HID];   // layer-1 output (relu'd)
__device__ float g_mean[(size_t)NN * HID];   // mean-aggregated features
__device__ __nv_bfloat16 g_Bhi[2 * HID * 2 * HID];  // [layer][j(128)][k(256)] hi part
__device__ __nv_bfloat16 g_Blo[2 * HID * 2 * HID];  // lo part
__device__ int   g_cnt [NN];
__device__ int   g_rowstart[NN];
__device__ int   g_cursor  [NN];
__device__ int   g_csr [EE];
__device__ int   g_bsum[256];

// ---------------- CSR build ----------------
__global__ void k_zero_cnt(int n) {
    int i = blockIdx.x * blockDim.x + threadIdx.x;
    if (i < n) g_cnt[i] = 0;
}

__global__ void k_hist(const int* __restrict__ dst, int e) {
    int i = blockIdx.x * blockDim.x + threadIdx.x;
    if (i < e) atomicAdd(&g_cnt[dst[i]], 1);
}

__global__ void k_scanA(int n) {
    __shared__ int s[1024];
    int i = blockIdx.x * 1024 + threadIdx.x;
    int v = (i < n) ? g_cnt[i] : 0;
    s[threadIdx.x] = v;
    __syncthreads();
    #pragma unroll
    for (int off = 1; off < 1024; off <<= 1) {
        int t = (threadIdx.x >= off) ? s[threadIdx.x - off] : 0;
        __syncthreads();
        s[threadIdx.x] += t;
        __syncthreads();
    }
    if (i < n) g_rowstart[i] = s[threadIdx.x] - v;   // exclusive within block
    if (threadIdx.x == 1023) g_bsum[blockIdx.x] = s[1023];
}

// scanC now also folds in the cross-block prefix (block reduction of g_bsum)
__global__ void k_scanC(int n) {
    __shared__ int red[1024];
    int t = threadIdx.x;
    int v = (t < blockIdx.x) ? g_bsum[t] : 0;   // nb <= 98 < 1024
    red[t] = v;
    __syncthreads();
    #pragma unroll
    for (int off = 512; off > 0; off >>= 1) {
        if (t < off) red[t] += red[t + off];
        __syncthreads();
    }
    int base = red[0];
    int i = blockIdx.x * 1024 + t;
    if (i < n) {
        int rs = g_rowstart[i] + base;
        g_rowstart[i] = rs;
        g_cursor[i]   = rs;
    }
}

__global__ void k_fill(const int* __restrict__ src, const int* __restrict__ dst, int e) {
    int i = blockIdx.x * blockDim.x + threadIdx.x;
    if (i < e) {
        int p = atomicAdd(&g_cursor[dst[i]], 1);
        g_csr[p] = src[i];
    }
}

// ---------------- feature gather: h = emb[x] ----------------
__global__ void k_gather(const int* __restrict__ x, const float4* __restrict__ emb, int n) {
    int i = blockIdx.x * blockDim.x + threadIdx.x;
    int total = n * (HID / 4);
    if (i < total) {
        int node = i >> 5;
        int c    = i & 31;
        ((float4*)g_h)[i] = emb[(size_t)x[node] * 32 + c];
    }
}

// ---------------- weight pack: concat [Wl;Wr] -> bf16 hi/lo, B[j][k] ----------------
__global__ void k_pack(const float* __restrict__ Wl1, const float* __restrict__ Wr1,
                       const float* __restrict__ Wl2, const float* __restrict__ Wr2) {
    int idx = blockIdx.x * blockDim.x + threadIdx.x;   // 2*128*256 = 65536
    if (idx >= 2 * HID * 2 * HID) return;
    int layer = idx >> 15;
    int j = (idx >> 8) & 127;
    int k = idx & 255;
    const float* Wl = layer ? Wl2 : Wl1;
    const float* Wr = layer ? Wr2 : Wr1;
    float w = (k < 128) ? Wl[j * 128 + k] : Wr[j * 128 + (k - 128)];
    __nv_bfloat16 hi = __float2bfloat16_rn(w);
    float lo = w - __bfloat162float(hi);
    g_Bhi[idx] = hi;
    g_Blo[idx] = __float2bfloat16_rn(lo);
}

// ---------------- mean aggregation (one warp per node) ----------------
__global__ void k_agg(int layer, int n) {
    int gw   = (blockIdx.x * blockDim.x + threadIdx.x) >> 5;
    int lane = threadIdx.x & 31;
    if (gw >= n) return;
    const float4* h4 = (const float4*)(layer ? g_h1 : g_h);
    int deg = g_cnt[gw];
    int st  = g_rowstart[gw];
    float4 acc = make_float4(0.f, 0.f, 0.f, 0.f);
    for (int e = 0; e < deg; e++) {
        int s = g_csr[st + e];
        float4 v = h4[(size_t)s * 32 + lane];
        acc.x += v.x; acc.y += v.y; acc.z += v.z; acc.w += v.w;
    }
    float sc = 1.0f / (float)max(deg, 1);
    acc.x *= sc; acc.y *= sc; acc.z *= sc; acc.w *= sc;
    ((float4*)g_mean)[(size_t)gw * 32 + lane] = acc;
}

// ---------------- tensor-core GEMM: out = relu([mean|h] @ B^T + bias) ----------------
__device__ __forceinline__ void mma16816(float* d, const uint32_t* a, const uint32_t* b) {
    asm volatile(
        "mma.sync.aligned.m16n8k16.row.col.f32.bf16.bf16.f32 "
        "{%0,%1,%2,%3}, {%4,%5,%6,%7}, {%8,%9}, {%0,%1,%2,%3};\n"
        : "+f"(d[0]), "+f"(d[1]), "+f"(d[2]), "+f"(d[3])
        : "r"(a[0]), "r"(a[1]), "r"(a[2]), "r"(a[3]), "r"(b[0]), "r"(b[1]));
}

// CTA: 128 rows x 128 cols; 8 warps, warp = 16 rows x 128 cols.
// k-permutation: lane (c=l%4) loads float4 at k-offset 4c; mma-k {2c,2c+1,2c+8,2c+9}
// maps to memory-k {4c,4c+1,4c+2,4c+3} consistently on both A and B sides.
__global__ __launch_bounds__(256) void k_gemm(int layer, const float* __restrict__ bias,
                                              float* __restrict__ outparam, int n) {
    const float* Am = g_mean;
    const float* Ah = layer ? g_h1 : g_h;
    const __nv_bfloat16* Bh = g_Bhi + (size_t)layer * 32768;
    const __nv_bfloat16* Bl = g_Blo + (size_t)layer * 32768;
    float* out = layer ? outparam : g_h1;

    int w = threadIdx.x >> 5, l = threadIdx.x & 31;
    int c = l & 3, g = l >> 2;
    int r0 = blockIdx.x * 128 + w * 16;
    int rg  = min(r0 + g,     n - 1);
    int rg8 = min(r0 + g + 8, n - 1);

    float acc[16][4];
    #pragma unroll
    for (int nt = 0; nt < 16; nt++) {
        float b0 = __ldg(bias + nt * 8 + 2 * c);
        float b1 = __ldg(bias + nt * 8 + 2 * c + 1);
        acc[nt][0] = b0; acc[nt][1] = b1; acc[nt][2] = b0; acc[nt][3] = b1;
    }

    #pragma unroll
    for (int ks = 0; ks < 16; ks++) {
        const float* A = (ks < 8) ? Am : Ah;
        int ko = (ks * 16) & 127;
        float4 fa = *(const float4*)(A + (size_t)rg  * HID + ko + 4 * c);
        float4 fb = *(const float4*)(A + (size_t)rg8 * HID + ko + 4 * c);

        __nv_bfloat162 h0 = __floats2bfloat162_rn(fa.x, fa.y);
        __nv_bfloat162 h1 = __floats2bfloat162_rn(fb.x, fb.y);
        __nv_bfloat162 h2 = __floats2bfloat162_rn(fa.z, fa.w);
        __nv_bfloat162 h3 = __floats2bfloat162_rn(fb.z, fb.w);
        __nv_bfloat162 e0 = __floats2bfloat162_rn(fa.x - __low2float(h0), fa.y - __high2float(h0));
        __nv_bfloat162 e1 = __floats2bfloat162_rn(fb.x - __low2float(h1), fb.y - __high2float(h1));
        __nv_bfloat162 e2 = __floats2bfloat162_rn(fa.z - __low2float(h2), fa.w - __high2float(h2));
        __nv_bfloat162 e3 = __floats2bfloat162_rn(fb.z - __low2float(h3), fb.w - __high2float(h3));

        uint32_t ahi[4], alo[4];
        ahi[0] = *(uint32_t*)&h0; ahi[1] = *(uint32_t*)&h1;
        ahi[2] = *(uint32_t*)&h2; ahi[3] = *(uint32_t*)&h3;
        alo[0] = *(uint32_t*)&e0; alo[1] = *(uint32_t*)&e1;
        alo[2] = *(uint32_t*)&e2; alo[3] = *(uint32_t*)&e3;

        #pragma unroll
        for (int nt = 0; nt < 16; nt++) {
            int j = nt * 8 + g;
            size_t bofs = (size_t)j * 256 + ks * 16 + 4 * c;
            uint2 bhv = *(const uint2*)(Bh + bofs);
            uint2 blv = *(const uint2*)(Bl + bofs);
            mma16816(acc[nt], ahi, (const uint32_t*)&bhv);
            mma16816(acc[nt], alo, (const uint32_t*)&bhv);
            mma16816(acc[nt], ahi, (const uint32_t*)&blv);
        }
    }

    int row0 = r0 + g, row1 = r0 + g + 8;
    #pragma unroll
    for (int nt = 0; nt < 16; nt++) {
        int col = nt * 8 + 2 * c;
        if (row0 < n) {
            float2 o = make_float2(fmaxf(acc[nt][0], 0.f), fmaxf(acc[nt][1], 0.f));
            *(float2*)(out + (size_t)row0 * HID + col) = o;
        }
        if (row1 < n) {
            float2 o = make_float2(fmaxf(acc[nt][2], 0.f), fmaxf(acc[nt][3], 0.f));
            *(float2*)(out + (size_t)row1 * HID + col) = o;
        }
    }
}

// ---------------- launch ----------------
extern "C" void kernel_launch(void* const* d_in, const int* in_sizes, int n_in,
                              void* d_out, int out_size) {
    const int*   x    = (const int*)  d_in[0];
    const int*   ei   = (const int*)  d_in[1];
    const float* emb  = (const float*)d_in[2];
    const float* Wl1  = (const float*)d_in[3];
    const float* bl1  = (const float*)d_in[4];
    const float* Wr1  = (const float*)d_in[5];
    const float* Wl2  = (const float*)d_in[6];
    const float* bl2  = (const float*)d_in[7];
    const float* Wr2  = (const float*)d_in[8];

    int n = in_sizes[0];
    int e = in_sizes[1] / 2;
    const int* src = ei;
    const int* dst = ei + e;

    int nb = (n + 1023) / 1024;

    // h0 = emb[x]; weight packing
    k_gather<<<(n * 32 + 255) / 256, 256>>>(x, (const float4*)emb, n);
    k_pack  <<<(2 * HID * 2 * HID + 255) / 256, 256>>>(Wl1, Wr1, Wl2, Wr2);

    // CSR build (graph identical for both layers)
    k_zero_cnt<<<(n + 255) / 256, 256>>>(n);
    k_hist    <<<(e + 255) / 256, 256>>>(dst, e);
    k_scanA   <<<nb, 1024>>>(n);
    k_scanC   <<<nb, 1024>>>(n);
    k_fill    <<<(e + 255) / 256, 256>>>(src, dst, e);

    // layer 1
    k_agg <<<(n + 7) / 8,    256>>>(0, n);
    k_gemm<<<(n + 127) / 128, 256>>>(0, bl1, (float*)d_out, n);  // writes g_h1

    // layer 2
    k_agg <<<(n + 7) / 8,    256>>>(1, n);
    k_gemm<<<(n + 127) / 128, 256>>>(1, bl2, (float*)d_out, n);  // writes d_out
}

// round 5
// speedup vs baseline: 3.1965x; 1.4611x over previous
#include <cuda_runtime.h>
#include <cuda_fp16.h>
#include <stdint.h>

#define HID 128
#define NN 100000
#define EE 600000

// ---------------- scratch (static device globals; no allocs) ----------------
__device__ float  g_h   [(size_t)NN * HID];   // layer-0 input features
__device__ float  g_h1  [(size_t)NN * HID];   // layer-1 output (relu'd)
__device__ float  g_mean[(size_t)NN * HID];   // mean-aggregated features
__device__ __half g_W16 [2 * HID * 2 * HID];  // [layer][j(128)][k(256: Wl|Wr)] fp16
__device__ int    g_cnt [NN];
__device__ int    g_rowstart[NN];
__device__ int    g_cursor  [NN];
__device__ int    g_csr [EE];
__device__ int    g_bsum[256];

// ---------------- CSR build (round-2 proven chain) ----------------
__global__ void k_zero_cnt(int n) {
    int i = blockIdx.x * blockDim.x + threadIdx.x;
    if (i < n) g_cnt[i] = 0;
}

__global__ void k_hist(const int* __restrict__ dst, int e) {
    int i = blockIdx.x * blockDim.x + threadIdx.x;
    if (i < e) atomicAdd(&g_cnt[dst[i]], 1);
}

__global__ void k_scanA(int n) {
    __shared__ int s[1024];
    int i = blockIdx.x * 1024 + threadIdx.x;
    int v = (i < n) ? g_cnt[i] : 0;
    s[threadIdx.x] = v;
    __syncthreads();
    #pragma unroll
    for (int off = 1; off < 1024; off <<= 1) {
        int t = (threadIdx.x >= off) ? s[threadIdx.x - off] : 0;
        __syncthreads();
        s[threadIdx.x] += t;
        __syncthreads();
    }
    if (i < n) g_rowstart[i] = s[threadIdx.x] - v;   // exclusive within block
    if (threadIdx.x == 1023) g_bsum[blockIdx.x] = s[1023];
}

__global__ void k_scanB(int nb) {
    int acc = 0;
    for (int b = 0; b < nb; b++) { int v = g_bsum[b]; g_bsum[b] = acc; acc += v; }
}

__global__ void k_scanC(int n) {
    int i = blockIdx.x * 1024 + threadIdx.x;
    if (i < n) {
        int rs = g_rowstart[i] + g_bsum[blockIdx.x];
        g_rowstart[i] = rs;
        g_cursor[i]   = rs;
    }
}

__global__ void k_fill(const int* __restrict__ src, const int* __restrict__ dst, int e) {
    int i = blockIdx.x * blockDim.x + threadIdx.x;
    if (i < e) {
        int p = atomicAdd(&g_cursor[dst[i]], 1);
        g_csr[p] = src[i];
    }
}

// ---------------- feature gather: h = emb[x] ----------------
__global__ void k_gather(const int* __restrict__ x, const float4* __restrict__ emb, int n) {
    int i = blockIdx.x * blockDim.x + threadIdx.x;
    int total = n * (HID / 4);
    if (i < total) {
        int node = i >> 5;
        int c    = i & 31;
        ((float4*)g_h)[i] = emb[(size_t)x[node] * 32 + c];
    }
}

// ---------------- weight pack: concat [Wl;Wr] -> fp16, B[j][k(256)] ----------------
__global__ void k_pack(const float* __restrict__ Wl1, const float* __restrict__ Wr1,
                       const float* __restrict__ Wl2, const float* __restrict__ Wr2) {
    int idx = blockIdx.x * blockDim.x + threadIdx.x;   // 2*128*256 = 65536
    if (idx >= 2 * HID * 2 * HID) return;
    int layer = idx >> 15;
    int j = (idx >> 8) & 127;
    int k = idx & 255;
    const float* Wl = layer ? Wl2 : Wl1;
    const float* Wr = layer ? Wr2 : Wr1;
    float w = (k < 128) ? Wl[j * 128 + k] : Wr[j * 128 + (k - 128)];
    g_W16[idx] = __float2half_rn(w);
}

// ---------------- mean aggregation (one warp per node) ----------------
__global__ void k_agg(int layer, int n) {
    int gw   = (blockIdx.x * blockDim.x + threadIdx.x) >> 5;
    int lane = threadIdx.x & 31;
    if (gw >= n) return;
    const float4* h4 = (const float4*)(layer ? g_h1 : g_h);
    int deg = g_cnt[gw];
    int st  = g_rowstart[gw];
    float4 acc = make_float4(0.f, 0.f, 0.f, 0.f);
    for (int e = 0; e < deg; e++) {
        int s = g_csr[st + e];
        float4 v = h4[(size_t)s * 32 + lane];
        acc.x += v.x; acc.y += v.y; acc.z += v.z; acc.w += v.w;
    }
    float sc = 1.0f / (float)max(deg, 1);
    acc.x *= sc; acc.y *= sc; acc.z *= sc; acc.w *= sc;
    ((float4*)g_mean)[(size_t)gw * 32 + lane] = acc;
}

// ---------------- tensor-core GEMM: out = relu([mean|h] @ W^T + bias) ----------------
// fp16 2-pass with x2048 pre-scale: (2048*A) = Ahi + Alo exactly in fp16-normal range.
__device__ __forceinline__ void mma16816h(float* d, const uint32_t* a, const uint32_t* b) {
    asm volatile(
        "mma.sync.aligned.m16n8k16.row.col.f32.f16.f16.f32 "
        "{%0,%1,%2,%3}, {%4,%5,%6,%7}, {%8,%9}, {%0,%1,%2,%3};\n"
        : "+f"(d[0]), "+f"(d[1]), "+f"(d[2]), "+f"(d[3])
        : "r"(a[0]), "r"(a[1]), "r"(a[2]), "r"(a[3]), "r"(b[0]), "r"(b[1]));
}

// CTA: 128 rows x 128 cols; 8 warps, warp = 16 rows x 128 cols. (round-2 layout)
// k-permutation: lane (c=l%4) loads float4 at k-offset 4c; mma-k {2c,2c+1,2c+8,2c+9}
// maps to memory-k {4c..4c+3} consistently on both A and B sides.
__global__ __launch_bounds__(256) void k_gemm(int layer, const float* __restrict__ bias,
                                              float* __restrict__ outparam, int n) {
    const float* Am = g_mean;
    const float* Ah = layer ? g_h1 : g_h;
    const __half* W = g_W16 + (size_t)layer * 32768;
    float* out = layer ? outparam : g_h1;

    const float SC  = 2048.0f;
    const float ISC = 1.0f / 2048.0f;

    int w = threadIdx.x >> 5, l = threadIdx.x & 31;
    int c = l & 3, g = l >> 2;
    int r0 = blockIdx.x * 128 + w * 16;
    int rg  = min(r0 + g,     n - 1);
    int rg8 = min(r0 + g + 8, n - 1);

    float acc[16][4];
    #pragma unroll
    for (int nt = 0; nt < 16; nt++) {
        float b0 = __ldg(bias + nt * 8 + 2 * c) * SC;
        float b1 = __ldg(bias + nt * 8 + 2 * c + 1) * SC;
        acc[nt][0] = b0; acc[nt][1] = b1; acc[nt][2] = b0; acc[nt][3] = b1;
    }

    #pragma unroll
    for (int ks = 0; ks < 16; ks++) {
        const float* A = (ks < 8) ? Am : Ah;
        int ko = (ks * 16) & 127;
        float4 fa = *(const float4*)(A + (size_t)rg  * HID + ko + 4 * c);
        float4 fb = *(const float4*)(A + (size_t)rg8 * HID + ko + 4 * c);
        fa.x *= SC; fa.y *= SC; fa.z *= SC; fa.w *= SC;
        fb.x *= SC; fb.y *= SC; fb.z *= SC; fb.w *= SC;

        __half2 h0 = __floats2half2_rn(fa.x, fa.y);
        __half2 h1 = __floats2half2_rn(fb.x, fb.y);
        __half2 h2 = __floats2half2_rn(fa.z, fa.w);
        __half2 h3 = __floats2half2_rn(fb.z, fb.w);
        __half2 e0 = __floats2half2_rn(fa.x - __low2float(h0), fa.y - __high2float(h0));
        __half2 e1 = __floats2half2_rn(fb.x - __low2float(h1), fb.y - __high2float(h1));
        __half2 e2 = __floats2half2_rn(fa.z - __low2float(h2), fa.w - __high2float(h2));
        __half2 e3 = __floats2half2_rn(fb.z - __low2float(h3), fb.w - __high2float(h3));

        uint32_t ahi[4], alo[4];
        ahi[0] = *(uint32_t*)&h0; ahi[1] = *(uint32_t*)&h1;
        ahi[2] = *(uint32_t*)&h2; ahi[3] = *(uint32_t*)&h3;
        alo[0] = *(uint32_t*)&e0; alo[1] = *(uint32_t*)&e1;
        alo[2] = *(uint32_t*)&e2; alo[3] = *(uint32_t*)&e3;

        #pragma unroll
        for (int nt = 0; nt < 16; nt++) {
            int j = nt * 8 + g;
            size_t bofs = (size_t)j * 256 + ks * 16 + 4 * c;
            uint2 bv = *(const uint2*)(W + bofs);
            mma16816h(acc[nt], ahi, (const uint32_t*)&bv);
            mma16816h(acc[nt], alo, (const uint32_t*)&bv);
        }
    }

    int row0 = r0 + g, row1 = r0 + g + 8;
    #pragma unroll
    for (int nt = 0; nt < 16; nt++) {
        int col = nt * 8 + 2 * c;
        if (row0 < n) {
            float2 o = make_float2(fmaxf(acc[nt][0] * ISC, 0.f),
                                   fmaxf(acc[nt][1] * ISC, 0.f));
            *(float2*)(out + (size_t)row0 * HID + col) = o;
        }
        if (row1 < n) {
            float2 o = make_float2(fmaxf(acc[nt][2] * ISC, 0.f),
                                   fmaxf(acc[nt][3] * ISC, 0.f));
            *(float2*)(out + (size_t)row1 * HID + col) = o;
        }
    }
}

// ---------------- launch (round-2 proven order) ----------------
extern "C" void kernel_launch(void* const* d_in, const int* in_sizes, int n_in,
                              void* d_out, int out_size) {
    const int*   x    = (const int*)  d_in[0];
    const int*   ei   = (const int*)  d_in[1];
    const float* emb  = (const float*)d_in[2];
    const float* Wl1  = (const float*)d_in[3];
    const float* bl1  = (const float*)d_in[4];
    const float* Wr1  = (const float*)d_in[5];
    const float* Wl2  = (const float*)d_in[6];
    const float* bl2  = (const float*)d_in[7];
    const float* Wr2  = (const float*)d_in[8];

    int n = in_sizes[0];
    int e = in_sizes[1] / 2;
    const int* src = ei;
    const int* dst = ei + e;

    int nb = (n + 1023) / 1024;

    // h0 = emb[x]; weight packing
    k_gather<<<(n * 32 + 255) / 256, 256>>>(x, (const float4*)emb, n);
    k_pack  <<<(2 * HID * 2 * HID + 255) / 256, 256>>>(Wl1, Wr1, Wl2, Wr2);

    // CSR build (graph identical for both layers)
    k_zero_cnt<<<(n + 255) / 256, 256>>>(n);
    k_hist    <<<(e + 255) / 256, 256>>>(dst, e);
    k_scanA   <<<nb, 1024>>>(n);
    k_scanB   <<<1, 1>>>(nb);
    k_scanC   <<<nb, 1024>>>(n);
    k_fill    <<<(e + 255) / 256, 256>>>(src, dst, e);

    // layer 1
    k_agg <<<(n + 7) / 8,    256>>>(0, n);
    k_gemm<<<(n + 127) / 128, 256>>>(0, bl1, (float*)d_out, n);  // writes g_h1

    // layer 2
    k_agg <<<(n + 7) / 8,    256>>>(1, n);
    k_gemm<<<(n + 127) / 128, 256>>>(1, bl2, (float*)d_out, n);  // writes d_out
}